// round 8
// baseline (speedup 1.0000x reference)
#include <cuda_runtime.h>
#include <math.h>

// ---------------------------------------------------------------------------
// AdvancedAutoInformer — persistent megakernel (v7 = v6 with dynamic smem).
// Domain reduction: only token 3999 matters; block-local attention (BLOCK=20)
// => tokens [3980,4000) from x[3978..3999]. B=32, S=20, D=256, H=8, F=1024.
// One kernel, 148 CTAs x 512 threads, device-wide counter barriers.
// v6 features: duplicated-A smem (pre-packed f32x2 operands, no packing movs),
// LN/hcomb/final spread over all 148 CTAs, attention re-gridded to 128 CTAs.
// v7 fix: pool is dynamic shared memory (50688 B > 48 KB static limit).
// ---------------------------------------------------------------------------

#define NCTA  148
#define NTHR  512
#define NTOK  640
#define N1    (NTOK*256)
#define LA2   136          // duplicated-A row stride (2*64 + 8 pad)
#define LW    260
#define POOLF 12672        // 2*16*LA2 + 2*16*LW = 4352 + 8320
#define POOLB (POOLF*4)    // 50688 bytes of dynamic smem

// Scratch (static device arrays; zero runtime allocation).
__device__ __align__(16) float g_c1col[NTOK*768];
__device__ __align__(16) float g_hf  [N1];
__device__ __align__(16) float g_h   [N1];
__device__ __align__(16) float g_qkvp[4*NTOK*768];   // 12*N1: QKV / FF2 partials
__device__ __align__(16) float g_att [N1];
__device__ __align__(16) float g_part[12*N1];        // split-K partial chunks
__device__ unsigned g_bars[64];
__device__ unsigned g_done;

// ---------------- device-wide barrier (148 co-resident CTAs) ----------------
__device__ __forceinline__ void gsync(int id){
  __syncthreads();
  if (threadIdx.x == 0){
    __threadfence();                       // cumulative release
    atomicAdd(&g_bars[id], 1u);
    volatile unsigned* p = &g_bars[id];
    while (*p < NCTA) { }
    __threadfence();                       // acquire
  }
  __syncthreads();
}

// ---------------- f32x2 helpers ----------------
__device__ __forceinline__ void fma2(unsigned long long &d,
                                     unsigned long long a, unsigned long long b){
  asm("fma.rn.f32x2 %0, %1, %2, %0;" : "+l"(d) : "l"(a), "l"(b));
}
__device__ __forceinline__ void unpk(unsigned long long v, float& lo, float& hi){
  asm("mov.b64 {%0, %1}, %2;" : "=f"(lo), "=f"(hi) : "l"(v));
}

// ---------------------------------------------------------------------------
// GEMM phase: C[m][n] = sum_k Aeff[m][k0+k] * Wrow(n)[k0+k]   (NT layout)
// Aeff = A  (A2==nullptr)  or  relu(A + A2 + abias[k])  (FF1->FF2 fusion).
// Tile 64x256 per job, 512 threads, per-thread 4 rows x 8 cols. A stored in
// smem DUPLICATED ({a,a} pairs) so the inner loop loads ready-packed f32x2
// operands via broadcast LDS.128. Double-buffered smem.
// mode: 0 = raw partial store, 1 = relu(acc + bias).
// ---------------------------------------------------------------------------
__device__ void gemm_dev(float* pool,
    const float* __restrict__ A, const float* __restrict__ A2,
    const float* __restrict__ abias, int lda,
    const float* __restrict__ W0, const float* __restrict__ W1,
    int wsplit, int ldw,
    const float* __restrict__ bias, int mode,
    float* C, int N, int splitk, int klen)
{
  const int tiles_n = N >> 8;
  const int njobs = 10 * tiles_n * splitk;
  float* As = pool;                 // [2][16][LA2]  (duplicated pairs)
  float* Ws = pool + 2*16*LA2;      // [2][16][LW]
  const int tid = threadIdx.x;
  const int tx = tid & 31, ty = tid >> 5;
  const int lr = tid >> 2, lc = (tid & 3) * 4;

  for (int job = blockIdx.x; job < njobs; job += NCTA){
    int z    = job / (10*tiles_n);
    int rest = job - z*(10*tiles_n);
    int tm   = rest / tiles_n;
    int tn   = rest - tm*tiles_n;
    int m0 = tm*64, n0 = tn*256, k0 = z*klen;

    int nA = n0 + lr, nB = n0 + 128 + lr;
    const float* WrA = (nA < wsplit) ? W0 + nA*ldw : W1 + (nA - wsplit)*ldw;
    const float* WrB = (nB < wsplit) ? W0 + nB*ldw : W1 + (nB - wsplit)*ldw;
    const float* Ar  = A + (m0 + lr)*lda;           // deref only if tid<256
    const float* Ar2 = A2 ? A2 + (m0 + lr)*lda : nullptr;

    unsigned long long acc[16];
    #pragma unroll
    for (int q = 0; q < 16; q++) acc[q] = 0ULL;

    const int nslab = klen >> 4;
    float4 ra, rwa, rwb;
    {
      int kk = k0 + lc;
      if (tid < 256){
        ra = *(const float4*)(Ar + kk);
        if (A2){
          float4 rb = *(const float4*)(Ar2 + kk);
          float4 bb = *(const float4*)(abias + kk);
          ra.x = fmaxf(ra.x + rb.x + bb.x, 0.f);
          ra.y = fmaxf(ra.y + rb.y + bb.y, 0.f);
          ra.z = fmaxf(ra.z + rb.z + bb.z, 0.f);
          ra.w = fmaxf(ra.w + rb.w + bb.w, 0.f);
        }
      }
      rwa = *(const float4*)(WrA + kk);
      rwb = *(const float4*)(WrB + kk);
    }
    // store slab 0 -> buffer 0 (A duplicated: As[k][2m],[2m+1] = a)
    {
      if (tid < 256){
        *(float2*)&As[(lc+0)*LA2 + 2*lr] = make_float2(ra.x, ra.x);
        *(float2*)&As[(lc+1)*LA2 + 2*lr] = make_float2(ra.y, ra.y);
        *(float2*)&As[(lc+2)*LA2 + 2*lr] = make_float2(ra.z, ra.z);
        *(float2*)&As[(lc+3)*LA2 + 2*lr] = make_float2(ra.w, ra.w);
      }
      Ws[(lc+0)*LW + lr] = rwa.x; Ws[(lc+1)*LW + lr] = rwa.y;
      Ws[(lc+2)*LW + lr] = rwa.z; Ws[(lc+3)*LW + lr] = rwa.w;
      Ws[(lc+0)*LW + 128 + lr] = rwb.x; Ws[(lc+1)*LW + 128 + lr] = rwb.y;
      Ws[(lc+2)*LW + 128 + lr] = rwb.z; Ws[(lc+3)*LW + 128 + lr] = rwb.w;
    }
    __syncthreads();

    int p = 0;
    for (int s = 0; s < nslab; s++){
      if (s + 1 < nslab){
        int kk = k0 + (s+1)*16 + lc;
        if (tid < 256){
          ra = *(const float4*)(Ar + kk);
          if (A2){
            float4 rb = *(const float4*)(Ar2 + kk);
            float4 bb = *(const float4*)(abias + kk);
            ra.x = fmaxf(ra.x + rb.x + bb.x, 0.f);
            ra.y = fmaxf(ra.y + rb.y + bb.y, 0.f);
            ra.z = fmaxf(ra.z + rb.z + bb.z, 0.f);
            ra.w = fmaxf(ra.w + rb.w + bb.w, 0.f);
          }
        }
        rwa = *(const float4*)(WrA + kk);
        rwb = *(const float4*)(WrB + kk);
      }
      const float* Ab = As + p*16*LA2;
      const float* Wb = Ws + p*16*LW;
      #pragma unroll
      for (int k = 0; k < 16; k++){
        // broadcast loads of pre-packed {a,a} pairs
        ulonglong2 aA = *(const ulonglong2*)(Ab + k*LA2 + 8*ty);      // {a0,a0},{a1,a1}
        ulonglong2 aB = *(const ulonglong2*)(Ab + k*LA2 + 8*ty + 4);  // {a2,a2},{a3,a3}
        ulonglong2 wA = *(const ulonglong2*)(Wb + k*LW + tx*4);
        ulonglong2 wB = *(const ulonglong2*)(Wb + k*LW + 128 + tx*4);
        fma2(acc[ 0], aA.x, wA.x); fma2(acc[ 1], aA.x, wA.y);
        fma2(acc[ 2], aA.x, wB.x); fma2(acc[ 3], aA.x, wB.y);
        fma2(acc[ 4], aA.y, wA.x); fma2(acc[ 5], aA.y, wA.y);
        fma2(acc[ 6], aA.y, wB.x); fma2(acc[ 7], aA.y, wB.y);
        fma2(acc[ 8], aB.x, wA.x); fma2(acc[ 9], aB.x, wA.y);
        fma2(acc[10], aB.x, wB.x); fma2(acc[11], aB.x, wB.y);
        fma2(acc[12], aB.y, wA.x); fma2(acc[13], aB.y, wA.y);
        fma2(acc[14], aB.y, wB.x); fma2(acc[15], aB.y, wB.y);
      }
      if (s + 1 < nslab){
        float* Ab2 = As + (p^1)*16*LA2;
        float* Wb2 = Ws + (p^1)*16*LW;
        if (tid < 256){
          *(float2*)&Ab2[(lc+0)*LA2 + 2*lr] = make_float2(ra.x, ra.x);
          *(float2*)&Ab2[(lc+1)*LA2 + 2*lr] = make_float2(ra.y, ra.y);
          *(float2*)&Ab2[(lc+2)*LA2 + 2*lr] = make_float2(ra.z, ra.z);
          *(float2*)&Ab2[(lc+3)*LA2 + 2*lr] = make_float2(ra.w, ra.w);
        }
        Wb2[(lc+0)*LW + lr] = rwa.x; Wb2[(lc+1)*LW + lr] = rwa.y;
        Wb2[(lc+2)*LW + lr] = rwa.z; Wb2[(lc+3)*LW + lr] = rwa.w;
        Wb2[(lc+0)*LW + 128 + lr] = rwb.x; Wb2[(lc+1)*LW + 128 + lr] = rwb.y;
        Wb2[(lc+2)*LW + 128 + lr] = rwb.z; Wb2[(lc+3)*LW + 128 + lr] = rwb.w;
      }
      __syncthreads();
      p ^= 1;
    }

    // epilogue
    float* Cz = C + (long)z * 640 * N;
    #pragma unroll
    for (int r = 0; r < 4; r++){
      int m = m0 + ty*4 + r;
      float o0,o1,o2,o3,o4,o5,o6,o7;
      unpk(acc[r*4+0], o0, o1); unpk(acc[r*4+1], o2, o3);
      unpk(acc[r*4+2], o4, o5); unpk(acc[r*4+3], o6, o7);
      int na = n0 + tx*4, nb = n0 + 128 + tx*4;
      if (mode == 1){
        o0 = fmaxf(o0 + bias[na+0], 0.f); o1 = fmaxf(o1 + bias[na+1], 0.f);
        o2 = fmaxf(o2 + bias[na+2], 0.f); o3 = fmaxf(o3 + bias[na+3], 0.f);
        o4 = fmaxf(o4 + bias[nb+0], 0.f); o5 = fmaxf(o5 + bias[nb+1], 0.f);
        o6 = fmaxf(o6 + bias[nb+2], 0.f); o7 = fmaxf(o7 + bias[nb+3], 0.f);
      }
      *(float4*)&Cz[(long)m*N + na] = make_float4(o0,o1,o2,o3);
      *(float4*)&Cz[(long)m*N + nb] = make_float4(o4,o5,o6,o7);
    }
  }
}

// ---------------------------------------------------------------------------
// conv1 (C=16 -> D=256, k=3, SAME) + relu -> im2col layout in g_c1col.
// ---------------------------------------------------------------------------
__device__ void conv1_dev(float* pool, const float* __restrict__ x,
                          const float* __restrict__ w,
                          const float* __restrict__ bias){
  if (blockIdx.x < 32){
    float* xs = pool;                       // 23*16 floats
    int b = blockIdx.x, tid = threadIdx.x;
    for (int idx = tid; idx < 23*16; idx += NTHR){
      int j = idx >> 4, c = idx & 15;
      int t = 3978 + j;
      xs[idx] = (t < 4000) ? x[(b*4000 + t)*16 + c] : 0.f;
    }
    __syncthreads();
    if (tid < 256){
      int d = tid;
      float wr[48];
      #pragma unroll
      for (int q = 0; q < 48; q++) wr[q] = w[d*48 + q];
      float bb = bias[d];
      for (int p = 0; p < 22; p++){
        float val = 0.f;
        if (p < 21){
          float acc = bb;
          #pragma unroll
          for (int k = 0; k < 3; k++)
            #pragma unroll
            for (int c = 0; c < 16; c++)
              acc += wr[c*3 + k] * xs[(p + k)*16 + c];
          val = fmaxf(acc, 0.f);
        }
        #pragma unroll
        for (int k = 0; k < 3; k++){
          int i = p - k;
          if (i >= 0 && i < 20)
            g_c1col[(b*20 + i)*768 + d*3 + k] = val;
        }
      }
    }
    __syncthreads();
  }
}

// ---------------------------------------------------------------------------
// Warp-per-row LayerNorm family. Rows spread across ALL 148 CTAs:
// row = warp*148 + blockIdx.x  (warps 0..4 active).
// ---------------------------------------------------------------------------
__device__ __forceinline__ float wsum(float v){
  #pragma unroll
  for (int o = 16; o > 0; o >>= 1) v += __shfl_xor_sync(0xffffffffu, v, o);
  return v;
}

__device__ void ln_rows(const float* __restrict__ res,
                        const float* __restrict__ part, int nch, int chs,
                        const float* __restrict__ bias,
                        const float* __restrict__ g,
                        const float* __restrict__ bta,
                        float* __restrict__ out, int relu){
  int row = (threadIdx.x >> 5)*NCTA + blockIdx.x;
  if (row >= NTOK) return;
  int lane = threadIdx.x & 31;
  int base = row*256;
  float v[8];
  float s = 0.f;
  #pragma unroll
  for (int q = 0; q < 8; q++){
    int d = q*32 + lane;
    float t = bias[d];
    for (int c = 0; c < nch; c++) t += part[c*chs + base + d];
    if (res) t += res[base + d];
    if (relu) t = fmaxf(t, 0.f);
    v[q] = t; s += t;
  }
  float mean = wsum(s) * (1.f/256.f);
  float s2 = 0.f;
  #pragma unroll
  for (int q = 0; q < 8; q++){ float c = v[q]-mean; s2 += c*c; }
  float inv = rsqrtf(wsum(s2) * (1.f/256.f) + 1e-5f);
  #pragma unroll
  for (int q = 0; q < 8; q++){
    int d = q*32 + lane;
    out[base + d] = (v[q]-mean)*inv*g[d] + bta[d];
  }
}

// h = hf + (trend + tb) + sin(season + sb); dual partials: 4 chunks of 640x512.
__device__ void hcomb_dev(const float* __restrict__ tb,
                          const float* __restrict__ sb){
  int row = (threadIdx.x >> 5)*NCTA + blockIdx.x;
  if (row >= NTOK) return;
  int lane = threadIdx.x & 31;
  #pragma unroll
  for (int q = 0; q < 8; q++){
    int d = q*32 + lane;
    int o = row*512 + d;
    float tr = g_part[o] + g_part[2*N1 + o] + g_part[4*N1 + o] + g_part[6*N1 + o] + tb[d];
    float se = g_part[o+256] + g_part[2*N1+o+256] + g_part[4*N1+o+256] + g_part[6*N1+o+256] + sb[d];
    g_h[row*256 + d] = g_hf[row*256 + d] + tr + sinf(se);
  }
}

// ---------------------------------------------------------------------------
// Attention: 128 CTAs, one per (batch, head-pair). Stages reduced K,V for its
// two heads into smem, then warp-per-(head,token) compute (lane = dim).
// Fuses the QKV 4-chunk split-K reduce + bias.
// ---------------------------------------------------------------------------
__device__ void attn_dev(float* pool, const float* __restrict__ bias){
  if (blockIdx.x >= 128) return;
  int b = blockIdx.x >> 2, hp = blockIdx.x & 3;      // heads 2hp, 2hp+1
  int tid = threadIdx.x;
  float* sk = pool;             // [2][20][32]
  float* sv = pool + 1280;      // [2][20][32]
  const int CH = NTOK*768;
  for (int e = tid; e < 1280; e += NTHR){
    int hl = e / 640, rem = e - hl*640;
    int j = rem >> 5, t = rem & 31;
    int h = 2*hp + hl;
    int o = (b*20 + j)*768 + 256 + h*32 + t;
    sk[e] = g_qkvp[o] + g_qkvp[CH+o] + g_qkvp[2*CH+o] + g_qkvp[3*CH+o]
          + bias[256 + h*32 + t];
    o += 256;
    sv[e] = g_qkvp[o] + g_qkvp[CH+o] + g_qkvp[2*CH+o] + g_qkvp[3*CH+o]
          + bias[512 + h*32 + t];
  }
  __syncthreads();

  int w = tid >> 5, lane = tid & 31;
  for (int task = w; task < 40; task += 16){
    int hl = task / 20, i = task - hl*20;
    int h = 2*hp + hl;
    int qo = (b*20 + i)*768 + h*32 + lane;
    float q = g_qkvp[qo] + g_qkvp[CH+qo] + g_qkvp[2*CH+qo] + g_qkvp[3*CH+qo]
            + bias[h*32 + lane];
    float sc[20];
    float mx = -1e30f;
    #pragma unroll
    for (int j = 0; j < 20; j++){
      float p = q * sk[(hl*20 + j)*32 + lane];
      p = wsum(p) * 0.17677669529663687f;            // 1/sqrt(32)
      sc[j] = p;
      mx = fmaxf(mx, p);
    }
    float ssum = 0.f;
    #pragma unroll
    for (int j = 0; j < 20; j++){ sc[j] = expf(sc[j] - mx); ssum += sc[j]; }
    float inv = 1.f / ssum;
    float o = 0.f;
    #pragma unroll
    for (int j = 0; j < 20; j++) o += sc[j] * sv[(hl*20 + j)*32 + lane];
    g_att[(b*20 + i)*256 + h*32 + lane] = o * inv;
  }
}

// ---------------------------------------------------------------------------
// Final: out[b*16+c] = h[b,last,:] . fc_w[c,:] + fc_b[c]  (warp per output,
// spread over all CTAs).
// ---------------------------------------------------------------------------
__device__ void final_dev(const float* __restrict__ fw,
                          const float* __restrict__ fb,
                          float* __restrict__ out){
  int gw = (threadIdx.x >> 5)*NCTA + blockIdx.x;
  if (gw >= 512) return;
  int lane = threadIdx.x & 31;
  int b = gw >> 4, c = gw & 15;
  const float* hr = g_h + (b*20 + 19)*256;
  const float* wr = fw + c*256;
  float s = 0.f;
  #pragma unroll
  for (int q = 0; q < 8; q++){
    int d = q*32 + lane;
    s += hr[d]*wr[d];
  }
  s = wsum(s);
  if (lane == 0) out[gw] = s + fb[c];
}

// ---------------------------------------------------------------------------
__global__ void __launch_bounds__(NTHR, 1)
mega_kernel(const float* x,
            const float* c1w, const float* c1b,
            const float* c2w, const float* c2b,
            const float* lnfg, const float* lnfb,
            const float* tw, const float* tb,
            const float* sw, const float* sb,
            const float* aiw, const float* aib,
            const float* aow, const float* aob,
            const float* l1g, const float* l1b,
            const float* f1w, const float* f1b,
            const float* f2w, const float* f2b,
            const float* l2g, const float* l2b,
            const float* fcw, const float* fcb,
            float* out)
{
  extern __shared__ __align__(16) float pool[];
  int bar = 0;

  conv1_dev(pool, x, c1w, c1b);
  gsync(bar++);
  // conv2: 640x256, K=768, splitK 12 (klen 64) -> 12 chunks = exactly g_part
  gemm_dev(pool, g_c1col, nullptr, nullptr, 768, c2w, nullptr, 1<<30, 768,
           nullptr, 0, g_part, 256, 12, 64);
  gsync(bar++);
  ln_rows(nullptr, g_part, 12, N1, c2b, lnfg, lnfb, g_hf, 1);
  gsync(bar++);
  // trend|season concat: N=512, K=256, splitK 4 -> 4 chunks of 640x512 (8*N1)
  gemm_dev(pool, g_hf, nullptr, nullptr, 256, tw, sw, 256, 256,
           nullptr, 0, g_part, 512, 4, 64);
  gsync(bar++);
  hcomb_dev(tb, sb);
  gsync(bar++);

  for (int i = 0; i < 4; i++){
    // QKV: N=768, K=256, splitK 4 -> 4 chunks of 3*N1 = exactly g_qkvp
    gemm_dev(pool, g_h, nullptr, nullptr, 256, aiw + i*768*256, nullptr,
             1<<30, 256, nullptr, 0, g_qkvp, 768, 4, 64);
    gsync(bar++);
    attn_dev(pool, aib + i*768);
    gsync(bar++);
    // out-proj: N=256, K=256, splitK 8 (klen 32) -> 8 chunks (8*N1 <= g_part)
    gemm_dev(pool, g_att, nullptr, nullptr, 256, aow + i*256*256, nullptr,
             1<<30, 256, nullptr, 0, g_part, 256, 8, 32);
    gsync(bar++);
    ln_rows(g_h, g_part, 8, N1, aob + i*256, l1g + i*256, l1b + i*256, g_h, 0);
    gsync(bar++);
    // FF1: N=1024, K=256, splitK 2 (klen 128) -> RAW partials, 2 chunks of
    // 640x1024 (4*N1 each) at g_part[0..8*N1)
    gemm_dev(pool, g_h, nullptr, nullptr, 256, f1w + i*1024*256, nullptr,
             1<<30, 256, nullptr, 0, g_part, 1024, 2, 128);
    gsync(bar++);
    // FF2: N=256, K=1024, splitK 8 (klen 128) -> 8 chunks of N1 into g_qkvp
    // (12*N1 buffer, dead here). A = relu(p0 + p1 + ff1_bias) fused in load.
    gemm_dev(pool, g_part, g_part + 640*1024, f1b + i*1024, 1024,
             f2w + i*256*1024, nullptr, 1<<30, 1024,
             nullptr, 0, g_qkvp, 256, 8, 128);
    gsync(bar++);
    ln_rows(g_h, g_qkvp, 8, N1, f2b + i*256, l2g + i*256, l2b + i*256,
            g_h, 0);
    gsync(bar++);
  }

  final_dev(fcw, fcb, out);

  // termination + reset for next graph replay
  __syncthreads();
  if (threadIdx.x == 0){
    __threadfence();
    unsigned old = atomicAdd(&g_done, 1u);
    if (old == NCTA - 1){
      #pragma unroll
      for (int i = 0; i < 64; i++) g_bars[i] = 0;
      g_done = 0;
      __threadfence();
    }
  }
}

// ---------------------------------------------------------------------------
extern "C" void kernel_launch(void* const* d_in, const int* in_sizes, int n_in,
                              void* d_out, int out_size){
  (void)in_sizes; (void)n_in; (void)out_size;
  cudaFuncSetAttribute(mega_kernel,
                       cudaFuncAttributeMaxDynamicSharedMemorySize, POOLB);
  mega_kernel<<<NCTA, NTHR, POOLB>>>(
      (const float*)d_in[0],  (const float*)d_in[1],  (const float*)d_in[2],
      (const float*)d_in[3],  (const float*)d_in[4],  (const float*)d_in[5],
      (const float*)d_in[6],  (const float*)d_in[7],  (const float*)d_in[8],
      (const float*)d_in[9],  (const float*)d_in[10], (const float*)d_in[11],
      (const float*)d_in[12], (const float*)d_in[13], (const float*)d_in[14],
      (const float*)d_in[15], (const float*)d_in[16], (const float*)d_in[17],
      (const float*)d_in[18], (const float*)d_in[19], (const float*)d_in[20],
      (const float*)d_in[21], (const float*)d_in[22], (const float*)d_in[23],
      (const float*)d_in[24], (float*)d_out);
}

// round 9
// speedup vs baseline: 1.0253x; 1.0253x over previous
#include <cuda_runtime.h>
#include <math.h>

// ---------------------------------------------------------------------------
// AdvancedAutoInformer — persistent megakernel (v8).
// Domain reduction: only token 3999 matters; block-local attention (BLOCK=20)
// => tokens [3980,4000) from x[3978..3999]. B=32, S=20, D=256, H=8, F=1024.
// One kernel, 148 CTAs x 512 threads, device-wide counter barriers.
// v8: GEMM tile 128x256 with 8x8 per-thread microtile (FMA-bound, not
// smem-crossbar-bound), all phases rebalanced to single-wave job grids with
// larger split-K (scratch enlarged to hold up to 24 partial chunks).
// ---------------------------------------------------------------------------

#define NCTA  148
#define NTHR  512
#define NTOK  640
#define N1    (NTOK*256)
#define LA2   264          // duplicated-A row stride (2*128 + 8 pad)
#define LW    260
#define POOLF 16768        // 2*16*LA2 + 2*16*LW = 8448 + 8320
#define POOLB (POOLF*4)    // 67072 bytes of dynamic smem

// Scratch (static device arrays; zero runtime allocation).
__device__ __align__(16) float g_c1col[NTOK*768];
__device__ __align__(16) float g_hf  [N1];
__device__ __align__(16) float g_h   [N1];
__device__ __align__(16) float g_qkvp[24*N1];   // QKV (8x3N1) / FF2 (16xN1) partials
__device__ __align__(16) float g_att [N1];
__device__ __align__(16) float g_part[24*N1];   // generic split-K partial chunks
__device__ unsigned g_bars[64];
__device__ unsigned g_done;

// ---------------- device-wide barrier (148 co-resident CTAs) ----------------
__device__ __forceinline__ void gsync(int id){
  __syncthreads();
  if (threadIdx.x == 0){
    __threadfence();                       // cumulative release
    atomicAdd(&g_bars[id], 1u);
    volatile unsigned* p = &g_bars[id];
    while (*p < NCTA) { }
    __threadfence();                       // acquire
  }
  __syncthreads();
}

// ---------------- f32x2 helpers ----------------
__device__ __forceinline__ void fma2(unsigned long long &d,
                                     unsigned long long a, unsigned long long b){
  asm("fma.rn.f32x2 %0, %1, %2, %0;" : "+l"(d) : "l"(a), "l"(b));
}
__device__ __forceinline__ void unpk(unsigned long long v, float& lo, float& hi){
  asm("mov.b64 {%0, %1}, %2;" : "=f"(lo), "=f"(hi) : "l"(v));
}

// ---------------------------------------------------------------------------
// GEMM phase: C[m][n] = sum_k Aeff[m][k0+k] * Wrow(n)[k0+k]   (NT layout)
// Aeff = A                      (a2count == 1)
//      = relu(sum_{c<a2count} A[c*a2stride + ...] + abias[k])   (FF1->FF2)
// Tile 128x256 per job, 512 threads, per-thread 8 rows x 8 cols.
// A stored in smem DUPLICATED ({a,a} pairs): inner loop reads pre-packed
// f32x2 operands via broadcast LDS.128. Double-buffered smem. Raw partial
// chunk stores only (all bias/activation fused into consumers).
// Wrow(n) = W0 + n*ldw for n<wsplit else W1 + (n-wsplit)*ldw.
// ---------------------------------------------------------------------------
__device__ void gemm_dev(float* pool,
    const float* __restrict__ A, int a2count, long a2stride,
    const float* __restrict__ abias, int lda,
    const float* __restrict__ W0, const float* __restrict__ W1,
    int wsplit, int ldw,
    float* C, int N, int splitk, int klen)
{
  const int tiles_n = N >> 8;
  const int njobs = 5 * tiles_n * splitk;
  float* As = pool;                 // [2][16][LA2]  (duplicated pairs)
  float* Ws = pool + 2*16*LA2;      // [2][16][LW]
  const int tid = threadIdx.x;
  const int tx = tid & 31, ty = tid >> 5;       // ty 0..15 -> 8 rows each
  const int lr = tid >> 2, lc = (tid & 3) * 4;  // lr 0..127

  for (int job = blockIdx.x; job < njobs; job += NCTA){
    int z    = job / (5*tiles_n);
    int rest = job - z*(5*tiles_n);
    int tm   = rest / tiles_n;
    int tn   = rest - tm*tiles_n;
    int m0 = tm*128, n0 = tn*256, k0 = z*klen;

    int nA = n0 + lr, nB = n0 + 128 + lr;
    const float* WrA = (nA < wsplit) ? W0 + nA*ldw : W1 + (nA - wsplit)*ldw;
    const float* WrB = (nB < wsplit) ? W0 + nB*ldw : W1 + (nB - wsplit)*ldw;
    const float* Ar  = A + (long)(m0 + lr)*lda;

    unsigned long long acc[32];
    #pragma unroll
    for (int q = 0; q < 32; q++) acc[q] = 0ULL;

    const int nslab = klen >> 4;
    float4 ra, rwa, rwb;
    {
      int kk = k0 + lc;
      ra = *(const float4*)(Ar + kk);
      if (a2count > 1){
        for (int c = 1; c < a2count; c++){
          float4 rb = *(const float4*)(Ar + c*a2stride + kk);
          ra.x += rb.x; ra.y += rb.y; ra.z += rb.z; ra.w += rb.w;
        }
        float4 bb = *(const float4*)(abias + kk);
        ra.x = fmaxf(ra.x + bb.x, 0.f); ra.y = fmaxf(ra.y + bb.y, 0.f);
        ra.z = fmaxf(ra.z + bb.z, 0.f); ra.w = fmaxf(ra.w + bb.w, 0.f);
      }
      rwa = *(const float4*)(WrA + kk);
      rwb = *(const float4*)(WrB + kk);
    }
    // store slab 0 -> buffer 0 (A duplicated: As[k][2m],[2m+1] = a)
    {
      *(float2*)&As[(lc+0)*LA2 + 2*lr] = make_float2(ra.x, ra.x);
      *(float2*)&As[(lc+1)*LA2 + 2*lr] = make_float2(ra.y, ra.y);
      *(float2*)&As[(lc+2)*LA2 + 2*lr] = make_float2(ra.z, ra.z);
      *(float2*)&As[(lc+3)*LA2 + 2*lr] = make_float2(ra.w, ra.w);
      Ws[(lc+0)*LW + lr] = rwa.x; Ws[(lc+1)*LW + lr] = rwa.y;
      Ws[(lc+2)*LW + lr] = rwa.z; Ws[(lc+3)*LW + lr] = rwa.w;
      Ws[(lc+0)*LW + 128 + lr] = rwb.x; Ws[(lc+1)*LW + 128 + lr] = rwb.y;
      Ws[(lc+2)*LW + 128 + lr] = rwb.z; Ws[(lc+3)*LW + 128 + lr] = rwb.w;
    }
    __syncthreads();

    int p = 0;
    for (int s = 0; s < nslab; s++){
      if (s + 1 < nslab){
        int kk = k0 + (s+1)*16 + lc;
        ra = *(const float4*)(Ar + kk);
        if (a2count > 1){
          for (int c = 1; c < a2count; c++){
            float4 rb = *(const float4*)(Ar + c*a2stride + kk);
            ra.x += rb.x; ra.y += rb.y; ra.z += rb.z; ra.w += rb.w;
          }
          float4 bb = *(const float4*)(abias + kk);
          ra.x = fmaxf(ra.x + bb.x, 0.f); ra.y = fmaxf(ra.y + bb.y, 0.f);
          ra.z = fmaxf(ra.z + bb.z, 0.f); ra.w = fmaxf(ra.w + bb.w, 0.f);
        }
        rwa = *(const float4*)(WrA + kk);
        rwb = *(const float4*)(WrB + kk);
      }
      const float* Ab = As + p*16*LA2;
      const float* Wb = Ws + p*16*LW;
      #pragma unroll
      for (int k = 0; k < 16; k++){
        // 8 rows as 4 broadcast LDS.128 of pre-packed {a,a} pairs
        ulonglong2 aA = *(const ulonglong2*)(Ab + k*LA2 + 16*ty);      // rows 0,1
        ulonglong2 aB = *(const ulonglong2*)(Ab + k*LA2 + 16*ty + 4);  // rows 2,3
        ulonglong2 aC = *(const ulonglong2*)(Ab + k*LA2 + 16*ty + 8);  // rows 4,5
        ulonglong2 aD = *(const ulonglong2*)(Ab + k*LA2 + 16*ty + 12); // rows 6,7
        ulonglong2 wA = *(const ulonglong2*)(Wb + k*LW + tx*4);
        ulonglong2 wB = *(const ulonglong2*)(Wb + k*LW + 128 + tx*4);
        fma2(acc[ 0], aA.x, wA.x); fma2(acc[ 1], aA.x, wA.y);
        fma2(acc[ 2], aA.x, wB.x); fma2(acc[ 3], aA.x, wB.y);
        fma2(acc[ 4], aA.y, wA.x); fma2(acc[ 5], aA.y, wA.y);
        fma2(acc[ 6], aA.y, wB.x); fma2(acc[ 7], aA.y, wB.y);
        fma2(acc[ 8], aB.x, wA.x); fma2(acc[ 9], aB.x, wA.y);
        fma2(acc[10], aB.x, wB.x); fma2(acc[11], aB.x, wB.y);
        fma2(acc[12], aB.y, wA.x); fma2(acc[13], aB.y, wA.y);
        fma2(acc[14], aB.y, wB.x); fma2(acc[15], aB.y, wB.y);
        fma2(acc[16], aC.x, wA.x); fma2(acc[17], aC.x, wA.y);
        fma2(acc[18], aC.x, wB.x); fma2(acc[19], aC.x, wB.y);
        fma2(acc[20], aC.y, wA.x); fma2(acc[21], aC.y, wA.y);
        fma2(acc[22], aC.y, wB.x); fma2(acc[23], aC.y, wB.y);
        fma2(acc[24], aD.x, wA.x); fma2(acc[25], aD.x, wA.y);
        fma2(acc[26], aD.x, wB.x); fma2(acc[27], aD.x, wB.y);
        fma2(acc[28], aD.y, wA.x); fma2(acc[29], aD.y, wA.y);
        fma2(acc[30], aD.y, wB.x); fma2(acc[31], aD.y, wB.y);
      }
      if (s + 1 < nslab){
        float* Ab2 = As + (p^1)*16*LA2;
        float* Wb2 = Ws + (p^1)*16*LW;
        *(float2*)&Ab2[(lc+0)*LA2 + 2*lr] = make_float2(ra.x, ra.x);
        *(float2*)&Ab2[(lc+1)*LA2 + 2*lr] = make_float2(ra.y, ra.y);
        *(float2*)&Ab2[(lc+2)*LA2 + 2*lr] = make_float2(ra.z, ra.z);
        *(float2*)&Ab2[(lc+3)*LA2 + 2*lr] = make_float2(ra.w, ra.w);
        Wb2[(lc+0)*LW + lr] = rwa.x; Wb2[(lc+1)*LW + lr] = rwa.y;
        Wb2[(lc+2)*LW + lr] = rwa.z; Wb2[(lc+3)*LW + lr] = rwa.w;
        Wb2[(lc+0)*LW + 128 + lr] = rwb.x; Wb2[(lc+1)*LW + 128 + lr] = rwb.y;
        Wb2[(lc+2)*LW + 128 + lr] = rwb.z; Wb2[(lc+3)*LW + 128 + lr] = rwb.w;
      }
      __syncthreads();
      p ^= 1;
    }

    // epilogue: raw partial store, 8 rows x 8 cols per thread
    float* Cz = C + (long)z * 640 * N;
    #pragma unroll
    for (int r = 0; r < 8; r++){
      int m = m0 + ty*8 + r;
      float o0,o1,o2,o3,o4,o5,o6,o7;
      unpk(acc[r*4+0], o0, o1); unpk(acc[r*4+1], o2, o3);
      unpk(acc[r*4+2], o4, o5); unpk(acc[r*4+3], o6, o7);
      *(float4*)&Cz[(long)m*N + n0 + tx*4]       = make_float4(o0,o1,o2,o3);
      *(float4*)&Cz[(long)m*N + n0 + 128 + tx*4] = make_float4(o4,o5,o6,o7);
    }
  }
}

// ---------------------------------------------------------------------------
// conv1 (C=16 -> D=256, k=3, SAME) + relu -> im2col layout in g_c1col.
// ---------------------------------------------------------------------------
__device__ void conv1_dev(float* pool, const float* __restrict__ x,
                          const float* __restrict__ w,
                          const float* __restrict__ bias){
  if (blockIdx.x < 32){
    float* xs = pool;                       // 23*16 floats
    int b = blockIdx.x, tid = threadIdx.x;
    for (int idx = tid; idx < 23*16; idx += NTHR){
      int j = idx >> 4, c = idx & 15;
      int t = 3978 + j;
      xs[idx] = (t < 4000) ? x[(b*4000 + t)*16 + c] : 0.f;
    }
    __syncthreads();
    if (tid < 256){
      int d = tid;
      float wr[48];
      #pragma unroll
      for (int q = 0; q < 48; q++) wr[q] = w[d*48 + q];
      float bb = bias[d];
      for (int p = 0; p < 22; p++){
        float val = 0.f;
        if (p < 21){
          float acc = bb;
          #pragma unroll
          for (int k = 0; k < 3; k++)
            #pragma unroll
            for (int c = 0; c < 16; c++)
              acc += wr[c*3 + k] * xs[(p + k)*16 + c];
          val = fmaxf(acc, 0.f);
        }
        #pragma unroll
        for (int k = 0; k < 3; k++){
          int i = p - k;
          if (i >= 0 && i < 20)
            g_c1col[(b*20 + i)*768 + d*3 + k] = val;
        }
      }
    }
    __syncthreads();
  }
}

// ---------------------------------------------------------------------------
// Warp-per-row LayerNorm family. Rows spread across ALL 148 CTAs:
// row = warp*148 + blockIdx.x.
// ---------------------------------------------------------------------------
__device__ __forceinline__ float wsum(float v){
  #pragma unroll
  for (int o = 16; o > 0; o >>= 1) v += __shfl_xor_sync(0xffffffffu, v, o);
  return v;
}

__device__ void ln_rows(const float* __restrict__ res,
                        const float* __restrict__ part, int nch, int chs,
                        const float* __restrict__ bias,
                        const float* __restrict__ g,
                        const float* __restrict__ bta,
                        float* __restrict__ out, int relu){
  int row = (threadIdx.x >> 5)*NCTA + blockIdx.x;
  if (row >= NTOK) return;
  int lane = threadIdx.x & 31;
  int base = row*256;
  float v[8];
  float s = 0.f;
  #pragma unroll
  for (int q = 0; q < 8; q++){
    int d = q*32 + lane;
    float t = bias[d];
    for (int c = 0; c < nch; c++) t += part[(long)c*chs + base + d];
    if (res) t += res[base + d];
    if (relu) t = fmaxf(t, 0.f);
    v[q] = t; s += t;
  }
  float mean = wsum(s) * (1.f/256.f);
  float s2 = 0.f;
  #pragma unroll
  for (int q = 0; q < 8; q++){ float c = v[q]-mean; s2 += c*c; }
  float inv = rsqrtf(wsum(s2) * (1.f/256.f) + 1e-5f);
  #pragma unroll
  for (int q = 0; q < 8; q++){
    int d = q*32 + lane;
    out[base + d] = (v[q]-mean)*inv*g[d] + bta[d];
  }
}

// h = hf + (trend + tb) + sin(season + sb); dual partials: 8 chunks of 640x512.
__device__ void hcomb_dev(const float* __restrict__ tb,
                          const float* __restrict__ sb){
  int row = (threadIdx.x >> 5)*NCTA + blockIdx.x;
  if (row >= NTOK) return;
  int lane = threadIdx.x & 31;
  #pragma unroll
  for (int q = 0; q < 8; q++){
    int d = q*32 + lane;
    long o = (long)row*512 + d;
    float tr = tb[d], se = sb[d];
    #pragma unroll
    for (int z = 0; z < 8; z++){
      tr += g_part[(long)z*2*N1 + o];
      se += g_part[(long)z*2*N1 + o + 256];
    }
    g_h[row*256 + d] = g_hf[row*256 + d] + tr + sinf(se);
  }
}

// ---------------------------------------------------------------------------
// Attention: 128 CTAs, one per (batch, head-pair). Fuses the QKV 8-chunk
// split-K reduce + bias. Warp-per-(head,token) compute (lane = dim).
// ---------------------------------------------------------------------------
__device__ void attn_dev(float* pool, const float* __restrict__ bias){
  if (blockIdx.x >= 128) return;
  int b = blockIdx.x >> 2, hp = blockIdx.x & 3;      // heads 2hp, 2hp+1
  int tid = threadIdx.x;
  float* sk = pool;             // [2][20][32]
  float* sv = pool + 1280;      // [2][20][32]
  const long CH = (long)NTOK*768;
  for (int e = tid; e < 1280; e += NTHR){
    int hl = e / 640, rem = e - hl*640;
    int j = rem >> 5, t = rem & 31;
    int h = 2*hp + hl;
    long o = (long)(b*20 + j)*768 + 256 + h*32 + t;
    float kk = bias[256 + h*32 + t], vv = bias[512 + h*32 + t];
    #pragma unroll
    for (int c = 0; c < 8; c++){
      kk += g_qkvp[c*CH + o];
      vv += g_qkvp[c*CH + o + 256];
    }
    sk[e] = kk; sv[e] = vv;
  }
  __syncthreads();

  int w = tid >> 5, lane = tid & 31;
  for (int task = w; task < 40; task += 16){
    int hl = task / 20, i = task - hl*20;
    int h = 2*hp + hl;
    long qo = (long)(b*20 + i)*768 + h*32 + lane;
    float q = bias[h*32 + lane];
    #pragma unroll
    for (int c = 0; c < 8; c++) q += g_qkvp[c*CH + qo];
    float sc[20];
    float mx = -1e30f;
    #pragma unroll
    for (int j = 0; j < 20; j++){
      float p = q * sk[(hl*20 + j)*32 + lane];
      p = wsum(p) * 0.17677669529663687f;            // 1/sqrt(32)
      sc[j] = p;
      mx = fmaxf(mx, p);
    }
    float ssum = 0.f;
    #pragma unroll
    for (int j = 0; j < 20; j++){ sc[j] = expf(sc[j] - mx); ssum += sc[j]; }
    float inv = 1.f / ssum;
    float o = 0.f;
    #pragma unroll
    for (int j = 0; j < 20; j++) o += sc[j] * sv[(hl*20 + j)*32 + lane];
    g_att[(b*20 + i)*256 + h*32 + lane] = o * inv;
  }
}

// ---------------------------------------------------------------------------
// Final: out[b*16+c] = h[b,last,:] . fc_w[c,:] + fc_b[c]
// ---------------------------------------------------------------------------
__device__ void final_dev(const float* __restrict__ fw,
                          const float* __restrict__ fb,
                          float* __restrict__ out){
  int gw = (threadIdx.x >> 5)*NCTA + blockIdx.x;
  if (gw >= 512) return;
  int lane = threadIdx.x & 31;
  int b = gw >> 4, c = gw & 15;
  const float* hr = g_h + (b*20 + 19)*256;
  const float* wr = fw + c*256;
  float s = 0.f;
  #pragma unroll
  for (int q = 0; q < 8; q++){
    int d = q*32 + lane;
    s += hr[d]*wr[d];
  }
  s = wsum(s);
  if (lane == 0) out[gw] = s + fb[c];
}

// ---------------------------------------------------------------------------
__global__ void __launch_bounds__(NTHR, 1)
mega_kernel(const float* x,
            const float* c1w, const float* c1b,
            const float* c2w, const float* c2b,
            const float* lnfg, const float* lnfb,
            const float* tw, const float* tb,
            const float* sw, const float* sb,
            const float* aiw, const float* aib,
            const float* aow, const float* aob,
            const float* l1g, const float* l1b,
            const float* f1w, const float* f1b,
            const float* f2w, const float* f2b,
            const float* l2g, const float* l2b,
            const float* fcw, const float* fcb,
            float* out)
{
  extern __shared__ __align__(16) float pool[];
  int bar = 0;

  conv1_dev(pool, x, c1w, c1b);
  gsync(bar++);
  // conv2: 640x256, K=768, splitK 24 (klen 32, 2 slabs) -> 24 chunks, 120 jobs
  gemm_dev(pool, g_c1col, 1, 0, nullptr, 768, c2w, nullptr, 1<<30, 768,
           g_part, 256, 24, 32);
  gsync(bar++);
  ln_rows(nullptr, g_part, 24, N1, c2b, lnfg, lnfb, g_hf, 1);
  gsync(bar++);
  // trend|season concat: N=512, K=256, splitK 8 (klen 32) -> 8 dual chunks, 80 jobs
  gemm_dev(pool, g_hf, 1, 0, nullptr, 256, tw, sw, 256, 256,
           g_part, 512, 8, 32);
  gsync(bar++);
  hcomb_dev(tb, sb);
  gsync(bar++);

  for (int i = 0; i < 4; i++){
    // QKV: N=768, K=256, splitK 8 (klen 32) -> 8 chunks of 3*N1, 120 jobs
    gemm_dev(pool, g_h, 1, 0, nullptr, 256, aiw + (long)i*768*256, nullptr,
             1<<30, 256, g_qkvp, 768, 8, 32);
    gsync(bar++);
    attn_dev(pool, aib + i*768);
    gsync(bar++);
    // out-proj: N=256, K=256, splitK 16 (klen 16, 1 slab) -> 16 chunks, 80 jobs
    gemm_dev(pool, g_att, 1, 0, nullptr, 256, aow + (long)i*256*256, nullptr,
             1<<30, 256, g_part, 256, 16, 16);
    gsync(bar++);
    ln_rows(g_h, g_part, 16, N1, aob + i*256, l1g + i*256, l1b + i*256, g_h, 0);
    gsync(bar++);
    // FF1: N=1024, K=256, splitK 4 (klen 64, 4 slabs) -> 4 chunks of 4*N1, 80 jobs
    gemm_dev(pool, g_h, 1, 0, nullptr, 256, f1w + (long)i*1024*256, nullptr,
             1<<30, 256, g_part, 1024, 4, 64);
    gsync(bar++);
    // FF2: N=256, K=1024, splitK 16 (klen 64, 4 slabs) -> 16 chunks into g_qkvp.
    // A = relu(p0+p1+p2+p3 + ff1_bias) fused into the A-tile load.
    gemm_dev(pool, g_part, 4, (long)4*N1, f1b + i*1024, 1024,
             f2w + (long)i*256*1024, nullptr, 1<<30, 1024,
             g_qkvp, 256, 16, 64);
    gsync(bar++);
    ln_rows(g_h, g_qkvp, 16, N1, f2b + i*256, l2g + i*256, l2b + i*256,
            g_h, 0);
    gsync(bar++);
  }

  final_dev(fcw, fcb, out);

  // termination + reset for next graph replay
  __syncthreads();
  if (threadIdx.x == 0){
    __threadfence();
    unsigned old = atomicAdd(&g_done, 1u);
    if (old == NCTA - 1){
      #pragma unroll
      for (int i = 0; i < 64; i++) g_bars[i] = 0;
      g_done = 0;
      __threadfence();
    }
  }
}

// ---------------------------------------------------------------------------
extern "C" void kernel_launch(void* const* d_in, const int* in_sizes, int n_in,
                              void* d_out, int out_size){
  (void)in_sizes; (void)n_in; (void)out_size;
  cudaFuncSetAttribute(mega_kernel,
                       cudaFuncAttributeMaxDynamicSharedMemorySize, POOLB);
  mega_kernel<<<NCTA, NTHR, POOLB>>>(
      (const float*)d_in[0],  (const float*)d_in[1],  (const float*)d_in[2],
      (const float*)d_in[3],  (const float*)d_in[4],  (const float*)d_in[5],
      (const float*)d_in[6],  (const float*)d_in[7],  (const float*)d_in[8],
      (const float*)d_in[9],  (const float*)d_in[10], (const float*)d_in[11],
      (const float*)d_in[12], (const float*)d_in[13], (const float*)d_in[14],
      (const float*)d_in[15], (const float*)d_in[16], (const float*)d_in[17],
      (const float*)d_in[18], (const float*)d_in[19], (const float*)d_in[20],
      (const float*)d_in[21], (const float*)d_in[22], (const float*)d_in[23],
      (const float*)d_in[24], (float*)d_out);
}

// round 13
// speedup vs baseline: 1.4778x; 1.4413x over previous
#include <cuda_runtime.h>
#include <cuda_bf16.h>
#include <cstdint>
#include <math.h>

// ---------------------------------------------------------------------------
// AdvancedAutoInformer — persistent megakernel (v12 = v11 resubmitted; round
// 12's bench was an infra failure, the kernel never ran).
// tcgen05 is unavailable (harness targets plain compute_100), so GEMM uses
// mma.sync.aligned.m16n8k16 bf16 (tensor pipe, baseline PTX) with a bf16
// hi/lo split of fp32 operands: D += Ah*Bh + Ah*Bl + Al*Bh (fp32 regs).
// Domain reduction: only token 3999 matters; block-local attention (BLOCK=20)
// => tokens [3980,4000). B=32, S=20, D=256, H=8, F=1024, L=4.
// One kernel, 148 CTAs x 512 threads, device-wide counter barriers.
// Job = 128x128 output tile; accumulators live across K-slabs (64/slab).
// ---------------------------------------------------------------------------

#define NCTA  148
#define NTHR  512
#define NTOK  640
#define N1    (NTOK*256)
#define POOLB 75776

// smem byte offsets: 4 bf16 tiles of 128 rows x 72 (stride) = 18432 B each
#define SM_AH 1024u
#define SM_AL 19456u
#define SM_BH 37888u
#define SM_BL 56320u

// Scratch (static device arrays; zero runtime allocation).
__device__ __align__(16) float g_c1col[NTOK*768];
__device__ __align__(16) float g_hf  [N1];
__device__ __align__(16) float g_h   [N1];
__device__ __align__(16) float g_qkvp[24*N1];   // QKV (4x3N1) / FF2 (8xN1) partials
__device__ __align__(16) float g_att [N1];
__device__ __align__(16) float g_part[24*N1];   // generic split-K partial chunks
__device__ unsigned g_bars[64];
__device__ unsigned g_done;

// ---------------- device-wide barrier (148 co-resident CTAs) ----------------
__device__ __forceinline__ void gsync(int id){
  __syncthreads();
  if (threadIdx.x == 0){
    __threadfence();
    atomicAdd(&g_bars[id], 1u);
    volatile unsigned* p = &g_bars[id];
    while (*p < NCTA) { }
    __threadfence();
  }
  __syncthreads();
}

// ---------------- bf16 mma.sync (m16n8k16, row.col, f32 accum) -------------
__device__ __forceinline__ void mma_bf16(float* c, const uint32_t* a,
                                         const uint32_t* b){
  asm volatile(
    "mma.sync.aligned.m16n8k16.row.col.f32.bf16.bf16.f32 "
    "{%0,%1,%2,%3},{%4,%5,%6,%7},{%8,%9},{%0,%1,%2,%3};"
    : "+f"(c[0]), "+f"(c[1]), "+f"(c[2]), "+f"(c[3])
    : "r"(a[0]), "r"(a[1]), "r"(a[2]), "r"(a[3]), "r"(b[0]), "r"(b[1]));
}

// pack hi/lo bf16x2 words of (v0, v1): hi = round(v), lo = round(v - hi)
__device__ __forceinline__ void split_pack(float v0, float v1,
                                           uint32_t& hw, uint32_t& lw){
  __nv_bfloat162 hp = __floats2bfloat162_rn(v0, v1);   // x = v0 (low half)
  __nv_bfloat162 lp = __floats2bfloat162_rn(v0 - __bfloat162float(hp.x),
                                            v1 - __bfloat162float(hp.y));
  hw = *(uint32_t*)&hp;
  lw = *(uint32_t*)&lp;
}

// ---------------------------------------------------------------------------
// Tensor GEMM phase: C[m][n] = sum_k Aeff[m][k0+k] * Wrow(n)[k0+k]  (NT)
// Aeff = A (a2count==1) or relu(sum_c A[c*a2stride+..] + abias[k]) (FF1->FF2).
// Job = 128x128 tile, z-th K-range of klen (slabs of 64). 16 warps 4x4,
// warp tile 32x32 = 2x4 m16n8 fragments. Raw fp32 partials to C + z*640*N.
// ---------------------------------------------------------------------------
__device__ void gemm_mma(char* sm,
    const float* __restrict__ A, int a2count, long a2stride,
    const float* __restrict__ abias, int lda,
    const float* __restrict__ W0, const float* __restrict__ W1,
    int wsplit, int ldw,
    float* C, int N, int splitk, int klen)
{
  const int tiles_n = N >> 7;
  const int njobs = 5 * tiles_n * splitk;
  const int tid = threadIdx.x;
  const int wid = tid >> 5, lane = tid & 31;
  const int wm = wid >> 2, wn = wid & 3;
  const int lr = lane >> 2, lc = lane & 3;

  uint32_t* AH = (uint32_t*)(sm + SM_AH);
  uint32_t* AL = (uint32_t*)(sm + SM_AL);
  uint32_t* BH = (uint32_t*)(sm + SM_BH);
  uint32_t* BL = (uint32_t*)(sm + SM_BL);

  // conversion-phase mapping: row = tid>>2, 16 k-elements starting at kb
  const int crow = tid >> 2;
  const int kb   = (tid & 3) << 4;
  const int kb2  = kb >> 1;               // word offset

  for (int job = blockIdx.x; job < njobs; job += NCTA){
    int z    = job / (5*tiles_n);
    int rest = job - z*(5*tiles_n);
    int tm_  = rest / tiles_n;
    int tn_  = rest - tm_*tiles_n;
    int m0 = tm_*128, n0 = tn_*128, k0 = z*klen;

    float acc[32];
    #pragma unroll
    for (int q = 0; q < 32; q++) acc[q] = 0.f;

    const int nslab = klen >> 6;
    for (int s = 0; s < nslab; s++){
      int ks = k0 + s*64;

      // ---- convert A tile (128 x 64) -> Ah/Al
      {
        const float* src = A + (long)(m0 + crow)*lda + ks + kb;
        float v[16];
        #pragma unroll
        for (int q = 0; q < 16; q += 4){
          float4 t = *(const float4*)(src + q);
          v[q] = t.x; v[q+1] = t.y; v[q+2] = t.z; v[q+3] = t.w;
        }
        if (a2count > 1){
          for (int c = 1; c < a2count; c++){
            const float* s2 = src + (long)c*a2stride;
            #pragma unroll
            for (int q = 0; q < 16; q += 4){
              float4 t = *(const float4*)(s2 + q);
              v[q] += t.x; v[q+1] += t.y; v[q+2] += t.z; v[q+3] += t.w;
            }
          }
          const float* bb = abias + ks + kb;
          #pragma unroll
          for (int q = 0; q < 16; q++) v[q] = fmaxf(v[q] + bb[q], 0.f);
        }
        uint32_t hw[8], lw[8];
        #pragma unroll
        for (int q = 0; q < 8; q++) split_pack(v[2*q], v[2*q+1], hw[q], lw[q]);
        int base = crow*36 + kb2;
        *(uint4*)(AH + base)     = make_uint4(hw[0],hw[1],hw[2],hw[3]);
        *(uint4*)(AH + base + 4) = make_uint4(hw[4],hw[5],hw[6],hw[7]);
        *(uint4*)(AL + base)     = make_uint4(lw[0],lw[1],lw[2],lw[3]);
        *(uint4*)(AL + base + 4) = make_uint4(lw[4],lw[5],lw[6],lw[7]);
      }
      // ---- convert B tile (128 W-rows x 64) -> Bh/Bl
      {
        int n = n0 + crow;
        const float* src = ((n < wsplit) ? W0 + (long)n*ldw
                                         : W1 + (long)(n - wsplit)*ldw) + ks + kb;
        float v[16];
        #pragma unroll
        for (int q = 0; q < 16; q += 4){
          float4 t = *(const float4*)(src + q);
          v[q] = t.x; v[q+1] = t.y; v[q+2] = t.z; v[q+3] = t.w;
        }
        uint32_t hw[8], lw[8];
        #pragma unroll
        for (int q = 0; q < 8; q++) split_pack(v[2*q], v[2*q+1], hw[q], lw[q]);
        int base = crow*36 + kb2;
        *(uint4*)(BH + base)     = make_uint4(hw[0],hw[1],hw[2],hw[3]);
        *(uint4*)(BH + base + 4) = make_uint4(hw[4],hw[5],hw[6],hw[7]);
        *(uint4*)(BL + base)     = make_uint4(lw[0],lw[1],lw[2],lw[3]);
        *(uint4*)(BL + base + 4) = make_uint4(lw[4],lw[5],lw[6],lw[7]);
      }
      __syncthreads();

      // ---- 4 k16-steps of mma
      const int aw0 = (wm*32 + lr)*36 + lc;
      const int bw0 = (wn*32 + lr)*36 + lc;
      #pragma unroll
      for (int s4 = 0; s4 < 4; s4++){
        const int ko2 = s4*8;
        uint32_t ah[2][4], al[2][4], bh[4][2], bl[4][2];
        #pragma unroll
        for (int t = 0; t < 2; t++){
          int o = aw0 + t*576 + ko2;
          ah[t][0] = AH[o];       ah[t][1] = AH[o + 288];
          ah[t][2] = AH[o + 4];   ah[t][3] = AH[o + 288 + 4];
          al[t][0] = AL[o];       al[t][1] = AL[o + 288];
          al[t][2] = AL[o + 4];   al[t][3] = AL[o + 288 + 4];
        }
        #pragma unroll
        for (int t = 0; t < 4; t++){
          int o = bw0 + t*288 + ko2;
          bh[t][0] = BH[o];  bh[t][1] = BH[o + 4];
          bl[t][0] = BL[o];  bl[t][1] = BL[o + 4];
        }
        #pragma unroll
        for (int tm = 0; tm < 2; tm++)
          #pragma unroll
          for (int tn = 0; tn < 4; tn++){
            float* c = &acc[(tm*4 + tn)*4];
            mma_bf16(c, ah[tm], bh[tn]);
            mma_bf16(c, ah[tm], bl[tn]);
            mma_bf16(c, al[tm], bh[tn]);
          }
      }
      __syncthreads();
    }

    // ---- epilogue: raw fp32 partial store
    float* Cz = C + (long)z*640*N;
    #pragma unroll
    for (int tm = 0; tm < 2; tm++)
      #pragma unroll
      for (int tn = 0; tn < 4; tn++){
        const float* c = &acc[(tm*4 + tn)*4];
        int row = m0 + wm*32 + tm*16 + lr;
        int col = n0 + wn*32 + tn*8 + 2*lc;
        *(float2*)&Cz[(long)row*N + col]       = make_float2(c[0], c[1]);
        *(float2*)&Cz[(long)(row + 8)*N + col] = make_float2(c[2], c[3]);
      }
  }
}

// ---------------------------------------------------------------------------
// conv1 (C=16 -> D=256, k=3, SAME) + relu -> im2col layout in g_c1col.
// ---------------------------------------------------------------------------
__device__ void conv1_dev(float* pool, const float* __restrict__ x,
                          const float* __restrict__ w,
                          const float* __restrict__ bias){
  if (blockIdx.x < 32){
    float* xs = pool;                       // 23*16 floats
    int b = blockIdx.x, tid = threadIdx.x;
    for (int idx = tid; idx < 23*16; idx += NTHR){
      int j = idx >> 4, c = idx & 15;
      int t = 3978 + j;
      xs[idx] = (t < 4000) ? x[(b*4000 + t)*16 + c] : 0.f;
    }
    __syncthreads();
    if (tid < 256){
      int d = tid;
      float wr[48];
      #pragma unroll
      for (int q = 0; q < 48; q++) wr[q] = w[d*48 + q];
      float bb = bias[d];
      for (int p = 0; p < 22; p++){
        float val = 0.f;
        if (p < 21){
          float acc = bb;
          #pragma unroll
          for (int k = 0; k < 3; k++)
            #pragma unroll
            for (int c = 0; c < 16; c++)
              acc += wr[c*3 + k] * xs[(p + k)*16 + c];
          val = fmaxf(acc, 0.f);
        }
        #pragma unroll
        for (int k = 0; k < 3; k++){
          int i = p - k;
          if (i >= 0 && i < 20)
            g_c1col[(b*20 + i)*768 + d*3 + k] = val;
        }
      }
    }
    __syncthreads();
  }
}

// ---------------------------------------------------------------------------
// Warp-per-row LayerNorm family. Rows spread across ALL 148 CTAs.
// ---------------------------------------------------------------------------
__device__ __forceinline__ float wsum(float v){
  #pragma unroll
  for (int o = 16; o > 0; o >>= 1) v += __shfl_xor_sync(0xffffffffu, v, o);
  return v;
}

__device__ void ln_rows(const float* __restrict__ res,
                        const float* __restrict__ part, int nch, long chs,
                        const float* __restrict__ bias,
                        const float* __restrict__ g,
                        const float* __restrict__ bta,
                        float* __restrict__ out, int relu){
  int row = (threadIdx.x >> 5)*NCTA + blockIdx.x;
  if (row >= NTOK) return;
  int lane = threadIdx.x & 31;
  int base = row*256;
  float v[8];
  float s = 0.f;
  #pragma unroll
  for (int q = 0; q < 8; q++){
    int d = q*32 + lane;
    float t = bias[d];
    for (int c = 0; c < nch; c++) t += part[(long)c*chs + base + d];
    if (res) t += res[base + d];
    if (relu) t = fmaxf(t, 0.f);
    v[q] = t; s += t;
  }
  float mean = wsum(s) * (1.f/256.f);
  float s2 = 0.f;
  #pragma unroll
  for (int q = 0; q < 8; q++){ float c = v[q]-mean; s2 += c*c; }
  float inv = rsqrtf(wsum(s2) * (1.f/256.f) + 1e-5f);
  #pragma unroll
  for (int q = 0; q < 8; q++){
    int d = q*32 + lane;
    out[base + d] = (v[q]-mean)*inv*g[d] + bta[d];
  }
}

// h = hf + (trend + tb) + sin(season + sb); dual partials: 4 chunks of 640x512.
__device__ void hcomb_dev(const float* __restrict__ tb,
                          const float* __restrict__ sb){
  int row = (threadIdx.x >> 5)*NCTA + blockIdx.x;
  if (row >= NTOK) return;
  int lane = threadIdx.x & 31;
  #pragma unroll
  for (int q = 0; q < 8; q++){
    int d = q*32 + lane;
    long o = (long)row*512 + d;
    float tr = tb[d], se = sb[d];
    #pragma unroll
    for (int z = 0; z < 4; z++){
      tr += g_part[(long)z*2*N1 + o];
      se += g_part[(long)z*2*N1 + o + 256];
    }
    g_h[row*256 + d] = g_hf[row*256 + d] + tr + sinf(se);
  }
}

// ---------------------------------------------------------------------------
// Attention: 128 CTAs, one per (batch, head-pair). Fuses the QKV 4-chunk
// split-K reduce + bias. Warp-per-(head,token) compute (lane = dim).
// ---------------------------------------------------------------------------
__device__ void attn_dev(float* pool, const float* __restrict__ bias){
  if (blockIdx.x >= 128) return;
  int b = blockIdx.x >> 2, hp = blockIdx.x & 3;      // heads 2hp, 2hp+1
  int tid = threadIdx.x;
  float* sk = pool;             // [2][20][32]
  float* sv = pool + 1280;      // [2][20][32]
  const long CH = (long)NTOK*768;
  for (int e = tid; e < 1280; e += NTHR){
    int hl = e / 640, rem = e - hl*640;
    int j = rem >> 5, t = rem & 31;
    int h = 2*hp + hl;
    long o = (long)(b*20 + j)*768 + 256 + h*32 + t;
    float kk = bias[256 + h*32 + t], vv = bias[512 + h*32 + t];
    #pragma unroll
    for (int c = 0; c < 4; c++){
      kk += g_qkvp[c*CH + o];
      vv += g_qkvp[c*CH + o + 256];
    }
    sk[e] = kk; sv[e] = vv;
  }
  __syncthreads();

  int w = tid >> 5, lane = tid & 31;
  for (int task = w; task < 40; task += 16){
    int hl = task / 20, i = task - hl*20;
    int h = 2*hp + hl;
    long qo = (long)(b*20 + i)*768 + h*32 + lane;
    float q = bias[h*32 + lane];
    #pragma unroll
    for (int c = 0; c < 4; c++) q += g_qkvp[c*CH + qo];
    float sc[20];
    float mx = -1e30f;
    #pragma unroll
    for (int j = 0; j < 20; j++){
      float p = q * sk[(hl*20 + j)*32 + lane];
      p = wsum(p) * 0.17677669529663687f;            // 1/sqrt(32)
      sc[j] = p;
      mx = fmaxf(mx, p);
    }
    float ssum = 0.f;
    #pragma unroll
    for (int j = 0; j < 20; j++){ sc[j] = expf(sc[j] - mx); ssum += sc[j]; }
    float inv = 1.f / ssum;
    float o = 0.f;
    #pragma unroll
    for (int j = 0; j < 20; j++) o += sc[j] * sv[(hl*20 + j)*32 + lane];
    g_att[(b*20 + i)*256 + h*32 + lane] = o * inv;
  }
}

// ---------------------------------------------------------------------------
// Final: out[b*16+c] = h[b,last,:] . fc_w[c,:] + fc_b[c]
// ---------------------------------------------------------------------------
__device__ void final_dev(const float* __restrict__ fw,
                          const float* __restrict__ fb,
                          float* __restrict__ out){
  int gw = (threadIdx.x >> 5)*NCTA + blockIdx.x;
  if (gw >= 512) return;
  int lane = threadIdx.x & 31;
  int b = gw >> 4, c = gw & 15;
  const float* hr = g_h + (b*20 + 19)*256;
  const float* wr = fw + c*256;
  float s = 0.f;
  #pragma unroll
  for (int q = 0; q < 8; q++){
    int d = q*32 + lane;
    s += hr[d]*wr[d];
  }
  s = wsum(s);
  if (lane == 0) out[gw] = s + fb[c];
}

// ---------------------------------------------------------------------------
__global__ void __launch_bounds__(NTHR, 1)
mega_kernel(const float* x,
            const float* c1w, const float* c1b,
            const float* c2w, const float* c2b,
            const float* lnfg, const float* lnfb,
            const float* tw, const float* tb,
            const float* sw, const float* sb,
            const float* aiw, const float* aib,
            const float* aow, const float* aob,
            const float* l1g, const float* l1b,
            const float* f1w, const float* f1b,
            const float* f2w, const float* f2b,
            const float* l2g, const float* l2b,
            const float* fcw, const float* fcb,
            float* out)
{
  extern __shared__ __align__(16) char smpool[];
  float* pool = (float*)smpool;
  int bar = 0;

  conv1_dev(pool, x, c1w, c1b);
  gsync(bar++);
  // conv2: K=768, splitK 12 (klen 64) -> 12 chunks of N1, 120 jobs
  gemm_mma(smpool, g_c1col, 1, 0, nullptr, 768,
           c2w, nullptr, 1<<30, 768, g_part, 256, 12, 64);
  gsync(bar++);
  ln_rows(nullptr, g_part, 12, N1, c2b, lnfg, lnfb, g_hf, 1);
  gsync(bar++);
  // trend|season concat: N=512, K=256, splitK 4 (klen 64) -> 4 dual chunks, 80 jobs
  gemm_mma(smpool, g_hf, 1, 0, nullptr, 256,
           tw, sw, 256, 256, g_part, 512, 4, 64);
  gsync(bar++);
  hcomb_dev(tb, sb);
  gsync(bar++);

  for (int i = 0; i < 4; i++){
    // QKV: N=768, K=256, splitK 4 (klen 64) -> 4 chunks of 3*N1, 120 jobs
    gemm_mma(smpool, g_h, 1, 0, nullptr, 256,
             aiw + (long)i*768*256, nullptr, 1<<30, 256, g_qkvp, 768, 4, 64);
    gsync(bar++);
    attn_dev(pool, aib + i*768);
    gsync(bar++);
    // out-proj: N=256, K=256, splitK 4 (klen 64) -> 4 chunks, 40 jobs
    gemm_mma(smpool, g_att, 1, 0, nullptr, 256,
             aow + (long)i*256*256, nullptr, 1<<30, 256, g_part, 256, 4, 64);
    gsync(bar++);
    ln_rows(g_h, g_part, 4, N1, aob + i*256, l1g + i*256, l1b + i*256, g_h, 0);
    gsync(bar++);
    // FF1: N=1024, K=256, splitK 2 (klen 128) -> 2 raw chunks of 4*N1, 80 jobs
    gemm_mma(smpool, g_h, 1, 0, nullptr, 256,
             f1w + (long)i*1024*256, nullptr, 1<<30, 256, g_part, 1024, 2, 128);
    gsync(bar++);
    // FF2: N=256, K=1024, splitK 8 (klen 128) -> 8 chunks into g_qkvp, 80 jobs.
    // A = relu(p0 + p1 + ff1_bias) fused into the A-tile conversion.
    gemm_mma(smpool, g_part, 2, (long)4*N1, f1b + i*1024, 1024,
             f2w + (long)i*256*1024, nullptr, 1<<30, 1024, g_qkvp, 256, 8, 128);
    gsync(bar++);
    ln_rows(g_h, g_qkvp, 8, N1, f2b + i*256, l2g + i*256, l2b + i*256,
            g_h, 0);
    gsync(bar++);
  }

  final_dev(fcw, fcb, out);

  // termination + reset for next graph replay
  __syncthreads();
  if (threadIdx.x == 0){
    __threadfence();
    unsigned old = atomicAdd(&g_done, 1u);
    if (old == NCTA - 1){
      #pragma unroll
      for (int i = 0; i < 64; i++) g_bars[i] = 0;
      g_done = 0;
      __threadfence();
    }
  }
}

// ---------------------------------------------------------------------------
extern "C" void kernel_launch(void* const* d_in, const int* in_sizes, int n_in,
                              void* d_out, int out_size){
  (void)in_sizes; (void)n_in; (void)out_size;
  cudaFuncSetAttribute(mega_kernel,
                       cudaFuncAttributeMaxDynamicSharedMemorySize, POOLB);
  mega_kernel<<<NCTA, NTHR, POOLB>>>(
      (const float*)d_in[0],  (const float*)d_in[1],  (const float*)d_in[2],
      (const float*)d_in[3],  (const float*)d_in[4],  (const float*)d_in[5],
      (const float*)d_in[6],  (const float*)d_in[7],  (const float*)d_in[8],
      (const float*)d_in[9],  (const float*)d_in[10], (const float*)d_in[11],
      (const float*)d_in[12], (const float*)d_in[13], (const float*)d_in[14],
      (const float*)d_in[15], (const float*)d_in[16], (const float*)d_in[17],
      (const float*)d_in[18], (const float*)d_in[19], (const float*)d_in[20],
      (const float*)d_in[21], (const float*)d_in[22], (const float*)d_in[23],
      (const float*)d_in[24], (float*)d_out);
}